// round 1
// baseline (speedup 1.0000x reference)
#include <cuda_runtime.h>
#include <cstdint>

#define N_MAX 100000
#define E_MAX 1000000
#define F_IN  64
#define F_HID 64
#define F_OUT 32

// ---------------- scratch (device globals; no allocation allowed) ----------------
__device__ float g_deg[2 * N_MAX];                 // [0..N): out-deg(src) -> norm_src ; [N..2N): in-deg(dst) -> norm_dst
__device__ float g_t1[(size_t)N_MAX * F_HID];      // (x*ns)@W1
__device__ float g_agg1[(size_t)N_MAX * F_HID];    // scatter result layer 1
__device__ float g_t2[(size_t)N_MAX * F_OUT];      // (relu(agg1*nd+b1)*ns)@W2

// ---------------- zero: degrees + agg1 + d_out ----------------
__global__ __launch_bounds__(256) void zero_kernel(float4* out4, int n_out4) {
    const int DEG4 = (2 * N_MAX) / 4;              // 50000
    const int AGG4 = (N_MAX * F_HID) / 4;          // 1600000
    int i = blockIdx.x * blockDim.x + threadIdx.x;
    float4 z = make_float4(0.f, 0.f, 0.f, 0.f);
    if (i < DEG4) {
        ((float4*)g_deg)[i] = z;
    } else if (i < DEG4 + AGG4) {
        ((float4*)g_agg1)[i - DEG4] = z;
    } else if (i < DEG4 + AGG4 + n_out4) {
        out4[i - DEG4 - AGG4] = z;
    }
}

// ---------------- degrees ----------------
__global__ __launch_bounds__(256) void degree_kernel(const int* __restrict__ src,
                                                     const int* __restrict__ dst, int e) {
    int i = blockIdx.x * blockDim.x + threadIdx.x;
    if (i < e) {
        atomicAdd(&g_deg[src[i]], 1.0f);
        atomicAdd(&g_deg[N_MAX + dst[i]], 1.0f);
    }
}

// deg -> clamped rsqrt norm (in place)
__global__ __launch_bounds__(256) void norm_kernel() {
    int i = blockIdx.x * blockDim.x + threadIdx.x;
    if (i < 2 * N_MAX) g_deg[i] = rsqrtf(fmaxf(g_deg[i], 1.0f));
}

// ---------------- GEMM 1: t1 = (x * norm_src) @ W1   (64 -> 64) ----------------
// 256 threads, 64 nodes/block, 4 threads/node each computing 16 outputs.
__global__ __launch_bounds__(256) void gemm1_kernel(const float* __restrict__ x,
                                                    const float* __restrict__ W1, int n) {
    __shared__ float sW[64 * 64];
    __shared__ float sX[64 * 64];
    int tid = threadIdx.x;
    int nb = blockIdx.x * 64;

    const float4* W4 = (const float4*)W1;
    float4* sW4 = (float4*)sW;
    #pragma unroll 4
    for (int idx = tid; idx < 64 * 16; idx += 256) sW4[idx] = W4[idx];

    const float4* x4 = (const float4*)x;
    float4* sX4 = (float4*)sX;
    #pragma unroll 4
    for (int idx = tid; idx < 64 * 16; idx += 256) {
        int row = idx >> 4;
        int node = nb + row;
        float4 v = make_float4(0.f, 0.f, 0.f, 0.f);
        if (node < n) {
            v = x4[(size_t)node * 16 + (idx & 15)];
            float ns = g_deg[node];
            v.x *= ns; v.y *= ns; v.z *= ns; v.w *= ns;
        }
        sX4[idx] = v;
    }
    __syncthreads();

    int nl = tid >> 2;      // local node 0..63
    int jq = tid & 3;       // output quarter (16 cols)
    float4 acc[4] = {};
    #pragma unroll 8
    for (int k = 0; k < 64; k++) {
        float xv = sX[nl * 64 + k];
        const float4* wr = (const float4*)&sW[k * 64 + jq * 16];
        #pragma unroll
        for (int u = 0; u < 4; u++) {
            float4 w = wr[u];
            acc[u].x += xv * w.x; acc[u].y += xv * w.y;
            acc[u].z += xv * w.z; acc[u].w += xv * w.w;
        }
    }
    int node = nb + nl;
    if (node < n) {
        float4* o = (float4*)&g_t1[(size_t)node * 64 + jq * 16];
        #pragma unroll
        for (int u = 0; u < 4; u++) o[u] = acc[u];
    }
}

// ---------------- scatter layer 1: agg1[dst] += t1[src]  (64 floats/edge) ----------------
__device__ __forceinline__ void red_v4(float* p, float4 v) {
    asm volatile("red.global.add.v4.f32 [%0], {%1,%2,%3,%4};"
                 :: "l"(p), "f"(v.x), "f"(v.y), "f"(v.z), "f"(v.w) : "memory");
}

__global__ __launch_bounds__(256) void scatter64_kernel(const int* __restrict__ src,
                                                        const int* __restrict__ dst, int e) {
    int gid = blockIdx.x * blockDim.x + threadIdx.x;
    int eidx = gid >> 4;
    if (eidx >= e) return;
    int c = gid & 15;
    int s = src[eidx];
    int d = dst[eidx];
    float4 v = ((const float4*)g_t1)[(size_t)s * 16 + c];
    red_v4(&g_agg1[(size_t)d * 64 + c * 4], v);
}

// ---------------- GEMM 2: t2 = (relu(agg1*nd + b1) * ns) @ W2   (64 -> 32) ----------------
// 256 threads, 128 nodes/block, 2 threads/node each computing 16 outputs.
__global__ __launch_bounds__(256) void gemm2_kernel(const float* __restrict__ b1,
                                                    const float* __restrict__ W2, int n) {
    __shared__ float sW[64 * 32];
    __shared__ float sX[128 * 64];
    int tid = threadIdx.x;
    int nb = blockIdx.x * 128;

    const float4* W4 = (const float4*)W2;
    float4* sW4 = (float4*)sW;
    #pragma unroll 2
    for (int idx = tid; idx < 64 * 8; idx += 256) sW4[idx] = W4[idx];

    const float4* a4 = (const float4*)g_agg1;
    const float4* b14 = (const float4*)b1;
    float4* sX4 = (float4*)sX;
    #pragma unroll 8
    for (int idx = tid; idx < 128 * 16; idx += 256) {
        int row = idx >> 4;
        int c = idx & 15;
        int node = nb + row;
        float4 v = make_float4(0.f, 0.f, 0.f, 0.f);
        if (node < n) {
            float nd = g_deg[N_MAX + node];
            float ns = g_deg[node];
            float4 a = a4[(size_t)node * 16 + c];
            float4 b = b14[c];
            v.x = fmaxf(fmaf(a.x, nd, b.x), 0.f) * ns;
            v.y = fmaxf(fmaf(a.y, nd, b.y), 0.f) * ns;
            v.z = fmaxf(fmaf(a.z, nd, b.z), 0.f) * ns;
            v.w = fmaxf(fmaf(a.w, nd, b.w), 0.f) * ns;
        }
        sX4[idx] = v;
    }
    __syncthreads();

    int nl = tid >> 1;      // local node 0..127
    int jq = tid & 1;       // output half (16 cols)
    float4 acc[4] = {};
    #pragma unroll 8
    for (int k = 0; k < 64; k++) {
        float xv = sX[nl * 64 + k];
        const float4* wr = (const float4*)&sW[k * 32 + jq * 16];
        #pragma unroll
        for (int u = 0; u < 4; u++) {
            float4 w = wr[u];
            acc[u].x += xv * w.x; acc[u].y += xv * w.y;
            acc[u].z += xv * w.z; acc[u].w += xv * w.w;
        }
    }
    int node = nb + nl;
    if (node < n) {
        float4* o = (float4*)&g_t2[(size_t)node * 32 + jq * 16];
        #pragma unroll
        for (int u = 0; u < 4; u++) o[u] = acc[u];
    }
}

// ---------------- scatter layer 2: d_out[dst] += t2[src]  (32 floats/edge) ----------------
__global__ __launch_bounds__(256) void scatter32_kernel(const int* __restrict__ src,
                                                        const int* __restrict__ dst,
                                                        float* __restrict__ out, int e) {
    int gid = blockIdx.x * blockDim.x + threadIdx.x;
    int eidx = gid >> 3;
    if (eidx >= e) return;
    int c = gid & 7;
    int s = src[eidx];
    int d = dst[eidx];
    float4 v = ((const float4*)g_t2)[(size_t)s * 8 + c];
    red_v4(&out[(size_t)d * 32 + c * 4], v);
}

// ---------------- final epilogue: out = relu(out * nd + b2), in place ----------------
__global__ __launch_bounds__(256) void final_kernel(float* __restrict__ out,
                                                    const float* __restrict__ b2, int n) {
    int i = blockIdx.x * blockDim.x + threadIdx.x;
    if (i >= n * 8) return;
    int row = i >> 3;
    int c = i & 7;
    float nd = g_deg[N_MAX + row];
    float4 b = ((const float4*)b2)[c];
    float4 v = ((float4*)out)[i];
    v.x = fmaxf(fmaf(v.x, nd, b.x), 0.f);
    v.y = fmaxf(fmaf(v.y, nd, b.y), 0.f);
    v.z = fmaxf(fmaf(v.z, nd, b.z), 0.f);
    v.w = fmaxf(fmaf(v.w, nd, b.w), 0.f);
    ((float4*)out)[i] = v;
}

// ---------------- launch ----------------
extern "C" void kernel_launch(void* const* d_in, const int* in_sizes, int n_in,
                              void* d_out, int out_size) {
    const float* x  = (const float*)d_in[0];
    const int*   ei = (const int*)d_in[1];
    const float* W1 = (const float*)d_in[2];
    const float* b1 = (const float*)d_in[3];
    const float* W2 = (const float*)d_in[4];
    const float* b2 = (const float*)d_in[5];
    float* out = (float*)d_out;

    int n = in_sizes[0] / F_IN;     // 100000
    int e = in_sizes[1] / 2;        // 1000000
    const int* src = ei;
    const int* dst = ei + e;

    // 1) zero degrees + agg1 + d_out
    int n_out4 = out_size / 4;
    int total4 = (2 * N_MAX) / 4 + (N_MAX * F_HID) / 4 + n_out4;
    zero_kernel<<<(total4 + 255) / 256, 256>>>((float4*)out, n_out4);

    // 2) degrees
    degree_kernel<<<(e + 255) / 256, 256>>>(src, dst, e);

    // 3) norms
    norm_kernel<<<(2 * N_MAX + 255) / 256, 256>>>();

    // 4) t1 = (x*ns)@W1
    gemm1_kernel<<<(n + 63) / 64, 256>>>(x, W1, n);

    // 5) agg1[dst] += t1[src]
    {
        long long threads = (long long)e * 16;
        scatter64_kernel<<<(int)((threads + 255) / 256), 256>>>(src, dst, e);
    }

    // 6) t2 = (relu(agg1*nd + b1)*ns)@W2
    gemm2_kernel<<<(n + 127) / 128, 256>>>(b1, W2, n);

    // 7) out[dst] += t2[src]
    {
        long long threads = (long long)e * 8;
        scatter32_kernel<<<(int)((threads + 255) / 256), 256>>>(src, dst, out, e);
    }

    // 8) out = relu(out*nd + b2)
    final_kernel<<<(n * 8 + 255) / 256, 256>>>(out, b2, n);
}

// round 2
// speedup vs baseline: 1.2600x; 1.2600x over previous
#include <cuda_runtime.h>
#include <cstdint>

#define N_MAX 100000
#define E_MAX 1000000
#define F_IN  64
#define F_HID 64
#define F_OUT 32

// ---------------- scratch (device globals; no allocation allowed) ----------------
__device__ float g_deg[2 * N_MAX];                 // [0..N): norm_src ; [N..2N): norm_dst
__device__ float g_t1[(size_t)N_MAX * F_HID];      // (x*ns)@W1
__device__ float g_agg1[(size_t)N_MAX * F_HID];    // scatter result layer 1
__device__ float g_t2[(size_t)N_MAX * F_OUT];      // (relu(agg1*nd+b1)*ns)@W2

// ---------------- zero: degrees + agg1 + d_out ----------------
__global__ __launch_bounds__(256) void zero_kernel(float4* out4, int n_out4) {
    const int DEG4 = (2 * N_MAX) / 4;
    const int AGG4 = (N_MAX * F_HID) / 4;
    int i = blockIdx.x * blockDim.x + threadIdx.x;
    float4 z = make_float4(0.f, 0.f, 0.f, 0.f);
    if (i < DEG4) {
        ((float4*)g_deg)[i] = z;
    } else if (i < DEG4 + AGG4) {
        ((float4*)g_agg1)[i - DEG4] = z;
    } else if (i < DEG4 + AGG4 + n_out4) {
        out4[i - DEG4 - AGG4] = z;
    }
}

// ---------------- degrees ----------------
__global__ __launch_bounds__(256) void degree_kernel(const int* __restrict__ src,
                                                     const int* __restrict__ dst, int e) {
    int i = blockIdx.x * blockDim.x + threadIdx.x;
    if (i < e) {
        atomicAdd(&g_deg[src[i]], 1.0f);
        atomicAdd(&g_deg[N_MAX + dst[i]], 1.0f);
    }
}

__global__ __launch_bounds__(256) void norm_kernel() {
    int i = blockIdx.x * blockDim.x + threadIdx.x;
    if (i < 2 * N_MAX) g_deg[i] = rsqrtf(fmaxf(g_deg[i], 1.0f));
}

// ---------------- GEMM 1: t1 = (x * norm_src) @ W1   (64 -> 64) ----------------
// 256 threads, 128 nodes/block. t = tid>>2 handles nodes (t, t+64); jq = tid&3
// handles 16 output cols. sX rows padded to 68 floats -> conflict-free LDS.
// W staged in two 32-row halves to fit 48KB static smem.
#define XPAD 68
__global__ __launch_bounds__(256) void gemm1_kernel(const float* __restrict__ x,
                                                    const float* __restrict__ W1, int n) {
    __shared__ float sW[32 * 64];        // 8 KB (one half of W at a time)
    __shared__ float sX[128 * XPAD];     // 34.8 KB
    int tid = threadIdx.x;
    int nb = blockIdx.x * 128;

    // stage X (scaled by norm_src), padded rows
    const float4* x4 = (const float4*)x;
    #pragma unroll 8
    for (int idx = tid; idx < 128 * 16; idx += 256) {
        int row = idx >> 4;
        int c = idx & 15;
        int node = nb + row;
        float4 v = make_float4(0.f, 0.f, 0.f, 0.f);
        if (node < n) {
            v = x4[(size_t)node * 16 + c];
            float ns = g_deg[node];
            v.x *= ns; v.y *= ns; v.z *= ns; v.w *= ns;
        }
        *(float4*)&sX[row * XPAD + c * 4] = v;
    }

    int t = tid >> 2;      // 0..63
    int jq = tid & 3;      // 16-col group
    float4 acc0[4] = {}, acc1[4] = {};
    const float4* W4 = (const float4*)W1;
    float4* sW4 = (float4*)sW;

    #pragma unroll
    for (int half = 0; half < 2; half++) {
        __syncthreads();   // protect sW reuse (also orders sX stage on first pass)
        #pragma unroll
        for (int idx = tid; idx < 32 * 16; idx += 256)
            sW4[idx] = W4[half * 512 + idx];
        __syncthreads();

        #pragma unroll 8
        for (int k2 = 0; k2 < 32; k2++) {
            float a0 = sX[t * XPAD + half * 32 + k2];
            float a1 = sX[(t + 64) * XPAD + half * 32 + k2];
            const float4* wr = (const float4*)&sW[k2 * 64 + jq * 16];
            #pragma unroll
            for (int u = 0; u < 4; u++) {
                float4 w = wr[u];
                acc0[u].x += a0 * w.x; acc0[u].y += a0 * w.y;
                acc0[u].z += a0 * w.z; acc0[u].w += a0 * w.w;
                acc1[u].x += a1 * w.x; acc1[u].y += a1 * w.y;
                acc1[u].z += a1 * w.z; acc1[u].w += a1 * w.w;
            }
        }
    }

    int n0 = nb + t;
    int n1 = nb + t + 64;
    if (n0 < n) {
        float4* o = (float4*)&g_t1[(size_t)n0 * 64 + jq * 16];
        #pragma unroll
        for (int u = 0; u < 4; u++) o[u] = acc0[u];
    }
    if (n1 < n) {
        float4* o = (float4*)&g_t1[(size_t)n1 * 64 + jq * 16];
        #pragma unroll
        for (int u = 0; u < 4; u++) o[u] = acc1[u];
    }
}

// ---------------- scatter layer 1: agg1[dst] += t1[src]  (64 floats/edge) ----------------
__device__ __forceinline__ void red_v4(float* p, float4 v) {
    asm volatile("red.global.add.v4.f32 [%0], {%1,%2,%3,%4};"
                 :: "l"(p), "f"(v.x), "f"(v.y), "f"(v.z), "f"(v.w) : "memory");
}

__global__ __launch_bounds__(256) void scatter64_kernel(const int* __restrict__ src,
                                                        const int* __restrict__ dst, int e) {
    int gid = blockIdx.x * blockDim.x + threadIdx.x;
    int eidx = gid >> 4;
    if (eidx >= e) return;
    int c = gid & 15;
    int s = src[eidx];
    int d = dst[eidx];
    float4 v = ((const float4*)g_t1)[(size_t)s * 16 + c];
    red_v4(&g_agg1[(size_t)d * 64 + c * 4], v);
}

// ---------------- GEMM 2: t2 = (relu(agg1*nd + b1) * ns) @ W2   (64 -> 32) ----------------
// 256 threads, 128 nodes/block. t = tid>>2 handles nodes (t, t+64); jq = tid&3
// handles 8 output cols (2 float4). Padded sX, conflict-free.
__global__ __launch_bounds__(256) void gemm2_kernel(const float* __restrict__ b1,
                                                    const float* __restrict__ W2, int n) {
    __shared__ float sW[64 * 32];        // 8 KB
    __shared__ float sX[128 * XPAD];     // 34.8 KB
    int tid = threadIdx.x;
    int nb = blockIdx.x * 128;

    const float4* W4 = (const float4*)W2;
    float4* sW4 = (float4*)sW;
    #pragma unroll
    for (int idx = tid; idx < 64 * 8; idx += 256) sW4[idx] = W4[idx];

    // stage X = relu(agg1*nd + b1) * ns, padded rows
    const float4* a4 = (const float4*)g_agg1;
    const float4* b14 = (const float4*)b1;
    #pragma unroll 8
    for (int idx = tid; idx < 128 * 16; idx += 256) {
        int row = idx >> 4;
        int c = idx & 15;
        int node = nb + row;
        float4 v = make_float4(0.f, 0.f, 0.f, 0.f);
        if (node < n) {
            float nd = g_deg[N_MAX + node];
            float ns = g_deg[node];
            float4 a = a4[(size_t)node * 16 + c];
            float4 b = b14[c];
            v.x = fmaxf(fmaf(a.x, nd, b.x), 0.f) * ns;
            v.y = fmaxf(fmaf(a.y, nd, b.y), 0.f) * ns;
            v.z = fmaxf(fmaf(a.z, nd, b.z), 0.f) * ns;
            v.w = fmaxf(fmaf(a.w, nd, b.w), 0.f) * ns;
        }
        *(float4*)&sX[row * XPAD + c * 4] = v;
    }
    __syncthreads();

    int t = tid >> 2;      // 0..63
    int jq = tid & 3;      // 8-col group
    float4 acc0[2] = {}, acc1[2] = {};
    #pragma unroll 8
    for (int k = 0; k < 64; k++) {
        float a0 = sX[t * XPAD + k];
        float a1 = sX[(t + 64) * XPAD + k];
        const float4* wr = (const float4*)&sW[k * 32 + jq * 8];
        #pragma unroll
        for (int u = 0; u < 2; u++) {
            float4 w = wr[u];
            acc0[u].x += a0 * w.x; acc0[u].y += a0 * w.y;
            acc0[u].z += a0 * w.z; acc0[u].w += a0 * w.w;
            acc1[u].x += a1 * w.x; acc1[u].y += a1 * w.y;
            acc1[u].z += a1 * w.z; acc1[u].w += a1 * w.w;
        }
    }

    int n0 = nb + t;
    int n1 = nb + t + 64;
    if (n0 < n) {
        float4* o = (float4*)&g_t2[(size_t)n0 * 32 + jq * 8];
        o[0] = acc0[0]; o[1] = acc0[1];
    }
    if (n1 < n) {
        float4* o = (float4*)&g_t2[(size_t)n1 * 32 + jq * 8];
        o[0] = acc1[0]; o[1] = acc1[1];
    }
}

// ---------------- scatter layer 2: d_out[dst] += t2[src]  (32 floats/edge) ----------------
__global__ __launch_bounds__(256) void scatter32_kernel(const int* __restrict__ src,
                                                        const int* __restrict__ dst,
                                                        float* __restrict__ out, int e) {
    int gid = blockIdx.x * blockDim.x + threadIdx.x;
    int eidx = gid >> 3;
    if (eidx >= e) return;
    int c = gid & 7;
    int s = src[eidx];
    int d = dst[eidx];
    float4 v = ((const float4*)g_t2)[(size_t)s * 8 + c];
    red_v4(&out[(size_t)d * 32 + c * 4], v);
}

// ---------------- final epilogue: out = relu(out * nd + b2), in place ----------------
__global__ __launch_bounds__(256) void final_kernel(float* __restrict__ out,
                                                    const float* __restrict__ b2, int n) {
    int i = blockIdx.x * blockDim.x + threadIdx.x;
    if (i >= n * 8) return;
    int row = i >> 3;
    int c = i & 7;
    float nd = g_deg[N_MAX + row];
    float4 b = ((const float4*)b2)[c];
    float4 v = ((float4*)out)[i];
    v.x = fmaxf(fmaf(v.x, nd, b.x), 0.f);
    v.y = fmaxf(fmaf(v.y, nd, b.y), 0.f);
    v.z = fmaxf(fmaf(v.z, nd, b.z), 0.f);
    v.w = fmaxf(fmaf(v.w, nd, b.w), 0.f);
    ((float4*)out)[i] = v;
}

// ---------------- launch ----------------
extern "C" void kernel_launch(void* const* d_in, const int* in_sizes, int n_in,
                              void* d_out, int out_size) {
    const float* x  = (const float*)d_in[0];
    const int*   ei = (const int*)d_in[1];
    const float* W1 = (const float*)d_in[2];
    const float* b1 = (const float*)d_in[3];
    const float* W2 = (const float*)d_in[4];
    const float* b2 = (const float*)d_in[5];
    float* out = (float*)d_out;

    int n = in_sizes[0] / F_IN;     // 100000
    int e = in_sizes[1] / 2;        // 1000000
    const int* src = ei;
    const int* dst = ei + e;

    int n_out4 = out_size / 4;
    int total4 = (2 * N_MAX) / 4 + (N_MAX * F_HID) / 4 + n_out4;
    zero_kernel<<<(total4 + 255) / 256, 256>>>((float4*)out, n_out4);

    degree_kernel<<<(e + 255) / 256, 256>>>(src, dst, e);
    norm_kernel<<<(2 * N_MAX + 255) / 256, 256>>>();

    gemm1_kernel<<<(n + 127) / 128, 256>>>(x, W1, n);

    {
        long long threads = (long long)e * 16;
        scatter64_kernel<<<(int)((threads + 255) / 256), 256>>>(src, dst, e);
    }

    gemm2_kernel<<<(n + 127) / 128, 256>>>(b1, W2, n);

    {
        long long threads = (long long)e * 8;
        scatter32_kernel<<<(int)((threads + 255) / 256), 256>>>(src, dst, out, e);
    }

    final_kernel<<<(n * 8 + 255) / 256, 256>>>(out, b2, n);
}

// round 3
// speedup vs baseline: 1.3760x; 1.0920x over previous
#include <cuda_runtime.h>
#include <cstdint>

#define N_MAX 100000
#define E_MAX 1000000
#define F_IN  64
#define F_HID 64
#define F_OUT 32
#define XPAD  68

// ---------------- scratch (device globals; no allocation allowed) ----------------
__device__ float g_deg[2 * N_MAX];                 // [0..N): norm_src ; [N..2N): norm_dst
__device__ float g_t1[(size_t)N_MAX * F_HID];      // (x*ns)@W1
__device__ float g_agg1[(size_t)N_MAX * F_HID];    // scatter result layer 1
__device__ float g_t2[(size_t)N_MAX * F_OUT];      // (relu(agg1*nd+b1)*ns)@W2

// ---------------- zero: degrees + agg1 + d_out ----------------
__global__ __launch_bounds__(256) void zero_kernel(float4* out4, int n_out4) {
    const int DEG4 = (2 * N_MAX) / 4;
    const int AGG4 = (N_MAX * F_HID) / 4;
    int i = blockIdx.x * blockDim.x + threadIdx.x;
    float4 z = make_float4(0.f, 0.f, 0.f, 0.f);
    if (i < DEG4) {
        ((float4*)g_deg)[i] = z;
    } else if (i < DEG4 + AGG4) {
        ((float4*)g_agg1)[i - DEG4] = z;
    } else if (i < DEG4 + AGG4 + n_out4) {
        out4[i - DEG4 - AGG4] = z;
    }
}

// ---------------- degrees ----------------
__global__ __launch_bounds__(256) void degree_kernel(const int* __restrict__ src,
                                                     const int* __restrict__ dst, int e) {
    int i = blockIdx.x * blockDim.x + threadIdx.x;
    if (i < e) {
        atomicAdd(&g_deg[src[i]], 1.0f);
        atomicAdd(&g_deg[N_MAX + dst[i]], 1.0f);
    }
}

__global__ __launch_bounds__(256) void norm_kernel() {
    int i = blockIdx.x * blockDim.x + threadIdx.x;
    if (i < 2 * N_MAX) g_deg[i] = rsqrtf(fmaxf(g_deg[i], 1.0f));
}

// ---------------- GEMM 1: t1 = (x * norm_src) @ W1   (64 -> 64) ----------------
// 128 threads, 256 nodes/block. trow = tid>>2 in [0,32); thread handles nodes
// trow + 32*i (i=0..7) and 16 output cols (jq = tid&3). sX in dynamic smem,
// rows padded to 68 floats (conflict-free). Full W (16KB) in static smem.
__global__ __launch_bounds__(128, 2) void gemm1_kernel(const float* __restrict__ x,
                                                       const float* __restrict__ W1, int n) {
    __shared__ float sW[64 * 64];            // 16 KB
    extern __shared__ float sX[];            // 256 * 68 * 4 = 69632 B
    int tid = threadIdx.x;
    int nb = blockIdx.x * 256;

    // stage full W
    const float4* W4 = (const float4*)W1;
    float4* sW4 = (float4*)sW;
    #pragma unroll
    for (int idx = tid; idx < 64 * 16; idx += 128) sW4[idx] = W4[idx];

    // stage X (scaled by norm_src), padded rows
    const float4* x4 = (const float4*)x;
    #pragma unroll 8
    for (int idx = tid; idx < 256 * 16; idx += 128) {
        int row = idx >> 4;
        int c = idx & 15;
        int node = nb + row;
        float4 v = make_float4(0.f, 0.f, 0.f, 0.f);
        if (node < n) {
            v = x4[(size_t)node * 16 + c];
            float ns = g_deg[node];
            v.x *= ns; v.y *= ns; v.z *= ns; v.w *= ns;
        }
        *(float4*)&sX[row * XPAD + c * 4] = v;
    }
    __syncthreads();

    int trow = tid >> 2;    // 0..31
    int jq = tid & 3;       // 16-col group
    float4 acc[8][4] = {};

    #pragma unroll 2
    for (int k = 0; k < 64; k++) {
        float a[8];
        #pragma unroll
        for (int i = 0; i < 8; i++) a[i] = sX[(trow + 32 * i) * XPAD + k];
        const float4* wr = (const float4*)&sW[k * 64 + jq * 16];
        float4 w0 = wr[0], w1 = wr[1], w2 = wr[2], w3 = wr[3];
        #pragma unroll
        for (int i = 0; i < 8; i++) {
            acc[i][0].x += a[i] * w0.x; acc[i][0].y += a[i] * w0.y;
            acc[i][0].z += a[i] * w0.z; acc[i][0].w += a[i] * w0.w;
            acc[i][1].x += a[i] * w1.x; acc[i][1].y += a[i] * w1.y;
            acc[i][1].z += a[i] * w1.z; acc[i][1].w += a[i] * w1.w;
            acc[i][2].x += a[i] * w2.x; acc[i][2].y += a[i] * w2.y;
            acc[i][2].z += a[i] * w2.z; acc[i][2].w += a[i] * w2.w;
            acc[i][3].x += a[i] * w3.x; acc[i][3].y += a[i] * w3.y;
            acc[i][3].z += a[i] * w3.z; acc[i][3].w += a[i] * w3.w;
        }
    }

    #pragma unroll
    for (int i = 0; i < 8; i++) {
        int node = nb + trow + 32 * i;
        if (node < n) {
            float4* o = (float4*)&g_t1[(size_t)node * 64 + jq * 16];
            o[0] = acc[i][0]; o[1] = acc[i][1]; o[2] = acc[i][2]; o[3] = acc[i][3];
        }
    }
}

// ---------------- scatter layer 1: agg1[dst] += t1[src]  (64 floats/edge) ----------------
__device__ __forceinline__ void red_v4(float* p, float4 v) {
    asm volatile("red.global.add.v4.f32 [%0], {%1,%2,%3,%4};"
                 :: "l"(p), "f"(v.x), "f"(v.y), "f"(v.z), "f"(v.w) : "memory");
}

__global__ __launch_bounds__(256) void scatter64_kernel(const int* __restrict__ src,
                                                        const int* __restrict__ dst, int e) {
    int gid = blockIdx.x * blockDim.x + threadIdx.x;
    int eidx = gid >> 4;
    if (eidx >= e) return;
    int c = gid & 15;
    int s = src[eidx];
    int d = dst[eidx];
    float4 v = ((const float4*)g_t1)[(size_t)s * 16 + c];
    red_v4(&g_agg1[(size_t)d * 64 + c * 4], v);
}

// ---------------- GEMM 2: t2 = (relu(agg1*nd + b1) * ns) @ W2   (64 -> 32) ----------------
// 128 threads, 256 nodes/block. Thread handles 8 nodes x 8 cols.
__global__ __launch_bounds__(128, 2) void gemm2_kernel(const float* __restrict__ b1,
                                                       const float* __restrict__ W2, int n) {
    __shared__ float sW[64 * 32];            // 8 KB
    extern __shared__ float sX[];            // 69632 B
    int tid = threadIdx.x;
    int nb = blockIdx.x * 256;

    const float4* W4 = (const float4*)W2;
    float4* sW4 = (float4*)sW;
    #pragma unroll
    for (int idx = tid; idx < 64 * 8; idx += 128) sW4[idx] = W4[idx];

    // stage X = relu(agg1*nd + b1) * ns, padded rows
    const float4* a4 = (const float4*)g_agg1;
    const float4* b14 = (const float4*)b1;
    #pragma unroll 8
    for (int idx = tid; idx < 256 * 16; idx += 128) {
        int row = idx >> 4;
        int c = idx & 15;
        int node = nb + row;
        float4 v = make_float4(0.f, 0.f, 0.f, 0.f);
        if (node < n) {
            float nd = g_deg[N_MAX + node];
            float ns = g_deg[node];
            float4 a = a4[(size_t)node * 16 + c];
            float4 b = b14[c];
            v.x = fmaxf(fmaf(a.x, nd, b.x), 0.f) * ns;
            v.y = fmaxf(fmaf(a.y, nd, b.y), 0.f) * ns;
            v.z = fmaxf(fmaf(a.z, nd, b.z), 0.f) * ns;
            v.w = fmaxf(fmaf(a.w, nd, b.w), 0.f) * ns;
        }
        *(float4*)&sX[row * XPAD + c * 4] = v;
    }
    __syncthreads();

    int trow = tid >> 2;    // 0..31
    int jq = tid & 3;       // 8-col group
    float4 acc[8][2] = {};

    #pragma unroll 4
    for (int k = 0; k < 64; k++) {
        float a[8];
        #pragma unroll
        for (int i = 0; i < 8; i++) a[i] = sX[(trow + 32 * i) * XPAD + k];
        const float4* wr = (const float4*)&sW[k * 32 + jq * 8];
        float4 w0 = wr[0], w1 = wr[1];
        #pragma unroll
        for (int i = 0; i < 8; i++) {
            acc[i][0].x += a[i] * w0.x; acc[i][0].y += a[i] * w0.y;
            acc[i][0].z += a[i] * w0.z; acc[i][0].w += a[i] * w0.w;
            acc[i][1].x += a[i] * w1.x; acc[i][1].y += a[i] * w1.y;
            acc[i][1].z += a[i] * w1.z; acc[i][1].w += a[i] * w1.w;
        }
    }

    #pragma unroll
    for (int i = 0; i < 8; i++) {
        int node = nb + trow + 32 * i;
        if (node < n) {
            float4* o = (float4*)&g_t2[(size_t)node * 32 + jq * 8];
            o[0] = acc[i][0]; o[1] = acc[i][1];
        }
    }
}

// ---------------- scatter layer 2: d_out[dst] += t2[src]  (32 floats/edge) ----------------
__global__ __launch_bounds__(256) void scatter32_kernel(const int* __restrict__ src,
                                                        const int* __restrict__ dst,
                                                        float* __restrict__ out, int e) {
    int gid = blockIdx.x * blockDim.x + threadIdx.x;
    int eidx = gid >> 3;
    if (eidx >= e) return;
    int c = gid & 7;
    int s = src[eidx];
    int d = dst[eidx];
    float4 v = ((const float4*)g_t2)[(size_t)s * 8 + c];
    red_v4(&out[(size_t)d * 32 + c * 4], v);
}

// ---------------- final epilogue: out = relu(out * nd + b2), in place ----------------
__global__ __launch_bounds__(256) void final_kernel(float* __restrict__ out,
                                                    const float* __restrict__ b2, int n) {
    int i = blockIdx.x * blockDim.x + threadIdx.x;
    if (i >= n * 8) return;
    int row = i >> 3;
    int c = i & 7;
    float nd = g_deg[N_MAX + row];
    float4 b = ((const float4*)b2)[c];
    float4 v = ((float4*)out)[i];
    v.x = fmaxf(fmaf(v.x, nd, b.x), 0.f);
    v.y = fmaxf(fmaf(v.y, nd, b.y), 0.f);
    v.z = fmaxf(fmaf(v.z, nd, b.z), 0.f);
    v.w = fmaxf(fmaf(v.w, nd, b.w), 0.f);
    ((float4*)out)[i] = v;
}

// ---------------- launch ----------------
extern "C" void kernel_launch(void* const* d_in, const int* in_sizes, int n_in,
                              void* d_out, int out_size) {
    const float* x  = (const float*)d_in[0];
    const int*   ei = (const int*)d_in[1];
    const float* W1 = (const float*)d_in[2];
    const float* b1 = (const float*)d_in[3];
    const float* W2 = (const float*)d_in[4];
    const float* b2 = (const float*)d_in[5];
    float* out = (float*)d_out;

    int n = in_sizes[0] / F_IN;     // 100000
    int e = in_sizes[1] / 2;        // 1000000
    const int* src = ei;
    const int* dst = ei + e;

    const int SX_BYTES = 256 * XPAD * 4;    // 69632
    cudaFuncSetAttribute(gemm1_kernel, cudaFuncAttributeMaxDynamicSharedMemorySize, SX_BYTES);
    cudaFuncSetAttribute(gemm2_kernel, cudaFuncAttributeMaxDynamicSharedMemorySize, SX_BYTES);

    int n_out4 = out_size / 4;
    int total4 = (2 * N_MAX) / 4 + (N_MAX * F_HID) / 4 + n_out4;
    zero_kernel<<<(total4 + 255) / 256, 256>>>((float4*)out, n_out4);

    degree_kernel<<<(e + 255) / 256, 256>>>(src, dst, e);
    norm_kernel<<<(2 * N_MAX + 255) / 256, 256>>>();

    gemm1_kernel<<<(n + 255) / 256, 128, SX_BYTES>>>(x, W1, n);

    {
        long long threads = (long long)e * 16;
        scatter64_kernel<<<(int)((threads + 255) / 256), 256>>>(src, dst, e);
    }

    gemm2_kernel<<<(n + 255) / 256, 128, SX_BYTES>>>(b1, W2, n);

    {
        long long threads = (long long)e * 8;
        scatter32_kernel<<<(int)((threads + 255) / 256), 256>>>(src, dst, out, e);
    }

    final_kernel<<<(n * 8 + 255) / 256, 256>>>(out, b2, n);
}

// round 4
// speedup vs baseline: 1.8254x; 1.3266x over previous
#include <cuda_runtime.h>
#include <cstdint>

#define N_MAX 100000
#define E_MAX 1000000
#define F_IN  64
#define F_HID 64
#define F_OUT 32
#define XPAD  68
#define SCAN_B 512

// ---------------- scratch (device globals; no allocation allowed) ----------------
__device__ int   g_indeg[N_MAX];
__device__ int   g_outdeg[N_MAX];
__device__ int   g_roff[N_MAX];                    // exclusive CSR offsets (by dst)
__device__ int   g_pos[N_MAX];                     // working copy for fill
__device__ int   g_bsum[256];                      // scan block sums
__device__ int   g_esrc[E_MAX];                    // CSR: src per in-edge, binned by dst
__device__ float g_deg[2 * N_MAX];                 // [0..N): norm_src ; [N..2N): norm_dst
__device__ float g_t1[(size_t)N_MAX * F_HID];      // (x*ns)@W1
__device__ float g_h[(size_t)N_MAX * F_HID];       // relu(agg1*nd+b1)*ns  (gemm2 input)
__device__ float g_t2[(size_t)N_MAX * F_OUT];      // h@W2

// ---------------- zero int degree arrays ----------------
__global__ __launch_bounds__(256) void zero_kernel() {
    int i = blockIdx.x * blockDim.x + threadIdx.x;
    if (i < N_MAX) { g_indeg[i] = 0; g_outdeg[i] = 0; }
}

// ---------------- degree count ----------------
__global__ __launch_bounds__(256) void count_kernel(const int* __restrict__ src,
                                                    const int* __restrict__ dst, int e) {
    int i = blockIdx.x * blockDim.x + threadIdx.x;
    if (i < e) {
        atomicAdd(&g_outdeg[src[i]], 1);
        atomicAdd(&g_indeg[dst[i]], 1);
    }
}

// ---------------- 2-level exclusive scan of g_indeg -> g_roff ----------------
__global__ __launch_bounds__(SCAN_B) void scan1_kernel(int n) {
    __shared__ int s[SCAN_B];
    int tid = threadIdx.x;
    int i = blockIdx.x * SCAN_B + tid;
    int v = (i < n) ? g_indeg[i] : 0;
    s[tid] = v;
    __syncthreads();
    #pragma unroll
    for (int off = 1; off < SCAN_B; off <<= 1) {
        int t = (tid >= off) ? s[tid - off] : 0;
        __syncthreads();
        s[tid] += t;
        __syncthreads();
    }
    if (i < n) g_roff[i] = s[tid];                 // inclusive for now
    if (tid == SCAN_B - 1) g_bsum[blockIdx.x] = s[tid];
}

__global__ __launch_bounds__(256) void scan2_kernel(int nblocks) {
    __shared__ int s[256];
    int tid = threadIdx.x;
    int v = (tid < nblocks) ? g_bsum[tid] : 0;
    s[tid] = v;
    __syncthreads();
    #pragma unroll
    for (int off = 1; off < 256; off <<= 1) {
        int t = (tid >= off) ? s[tid - off] : 0;
        __syncthreads();
        s[tid] += t;
        __syncthreads();
    }
    if (tid < nblocks) g_bsum[tid] = s[tid] - v;   // exclusive
}

__global__ __launch_bounds__(256) void scan3_kernel(int n) {
    int i = blockIdx.x * blockDim.x + threadIdx.x;
    if (i < n) {
        int off = g_roff[i] - g_indeg[i] + g_bsum[i / SCAN_B];  // global exclusive
        g_roff[i] = off;
        g_pos[i] = off;
    }
}

// ---------------- CSR fill ----------------
__global__ __launch_bounds__(256) void fill_kernel(const int* __restrict__ src,
                                                   const int* __restrict__ dst, int e) {
    int i = blockIdx.x * blockDim.x + threadIdx.x;
    if (i < e) {
        int p = atomicAdd(&g_pos[dst[i]], 1);
        g_esrc[p] = src[i];
    }
}

// ---------------- norms ----------------
__global__ __launch_bounds__(256) void norm_kernel(int n) {
    int i = blockIdx.x * blockDim.x + threadIdx.x;
    if (i < n) {
        g_deg[i]        = rsqrtf(fmaxf((float)g_outdeg[i], 1.0f));
        g_deg[N_MAX + i] = rsqrtf(fmaxf((float)g_indeg[i], 1.0f));
    }
}

// ---------------- GEMM 1: t1 = (x * norm_src) @ W1   (64 -> 64) ----------------
// 256 threads, 256 nodes/block. trow = tid>>2 in [0,64); thread handles nodes
// trow + 64*i (i=0..3) and 16 output cols (jq = tid&3).
__global__ __launch_bounds__(256, 2) void gemm1_kernel(const float* __restrict__ x,
                                                       const float* __restrict__ W1, int n) {
    __shared__ float sW[64 * 64];            // 16 KB
    extern __shared__ float sX[];            // 256 * 68 * 4 = 69632 B
    int tid = threadIdx.x;
    int nb = blockIdx.x * 256;

    const float4* W4 = (const float4*)W1;
    float4* sW4 = (float4*)sW;
    #pragma unroll
    for (int idx = tid; idx < 64 * 16; idx += 256) sW4[idx] = W4[idx];

    const float4* x4 = (const float4*)x;
    #pragma unroll 4
    for (int idx = tid; idx < 256 * 16; idx += 256) {
        int row = idx >> 4;
        int c = idx & 15;
        int node = nb + row;
        float4 v = make_float4(0.f, 0.f, 0.f, 0.f);
        if (node < n) {
            v = x4[(size_t)node * 16 + c];
            float ns = g_deg[node];
            v.x *= ns; v.y *= ns; v.z *= ns; v.w *= ns;
        }
        *(float4*)&sX[row * XPAD + c * 4] = v;
    }
    __syncthreads();

    int trow = tid >> 2;    // 0..63
    int jq = tid & 3;       // 16-col group
    float4 acc[4][4] = {};

    #pragma unroll 2
    for (int k = 0; k < 64; k++) {
        float a[4];
        #pragma unroll
        for (int i = 0; i < 4; i++) a[i] = sX[(trow + 64 * i) * XPAD + k];
        const float4* wr = (const float4*)&sW[k * 64 + jq * 16];
        float4 w0 = wr[0], w1 = wr[1], w2 = wr[2], w3 = wr[3];
        #pragma unroll
        for (int i = 0; i < 4; i++) {
            acc[i][0].x += a[i] * w0.x; acc[i][0].y += a[i] * w0.y;
            acc[i][0].z += a[i] * w0.z; acc[i][0].w += a[i] * w0.w;
            acc[i][1].x += a[i] * w1.x; acc[i][1].y += a[i] * w1.y;
            acc[i][1].z += a[i] * w1.z; acc[i][1].w += a[i] * w1.w;
            acc[i][2].x += a[i] * w2.x; acc[i][2].y += a[i] * w2.y;
            acc[i][2].z += a[i] * w2.z; acc[i][2].w += a[i] * w2.w;
            acc[i][3].x += a[i] * w3.x; acc[i][3].y += a[i] * w3.y;
            acc[i][3].z += a[i] * w3.z; acc[i][3].w += a[i] * w3.w;
        }
    }

    #pragma unroll
    for (int i = 0; i < 4; i++) {
        int node = nb + trow + 64 * i;
        if (node < n) {
            float4* o = (float4*)&g_t1[(size_t)node * 64 + jq * 16];
            o[0] = acc[i][0]; o[1] = acc[i][1]; o[2] = acc[i][2]; o[3] = acc[i][3];
        }
    }
}

// ---------------- gather 1: h = relu((sum t1[src]) * nd + b1) * ns ----------------
// 16 threads/node (one float4 col group each), 16 nodes/block.
__global__ __launch_bounds__(256) void gather1_kernel(const float* __restrict__ b1, int n) {
    int tid = threadIdx.x;
    int node = blockIdx.x * 16 + (tid >> 4);
    if (node >= n) return;
    int c = tid & 15;
    const float4* t14 = (const float4*)g_t1;
    int start = g_roff[node];
    int len = g_indeg[node];
    float4 acc = make_float4(0.f, 0.f, 0.f, 0.f);
    int j = 0;
    for (; j + 2 <= len; j += 2) {
        int s0 = g_esrc[start + j];
        int s1 = g_esrc[start + j + 1];
        float4 v0 = t14[(size_t)s0 * 16 + c];
        float4 v1 = t14[(size_t)s1 * 16 + c];
        acc.x += v0.x; acc.y += v0.y; acc.z += v0.z; acc.w += v0.w;
        acc.x += v1.x; acc.y += v1.y; acc.z += v1.z; acc.w += v1.w;
    }
    if (j < len) {
        int s0 = g_esrc[start + j];
        float4 v0 = t14[(size_t)s0 * 16 + c];
        acc.x += v0.x; acc.y += v0.y; acc.z += v0.z; acc.w += v0.w;
    }
    float nd = g_deg[N_MAX + node];
    float ns = g_deg[node];
    float4 b = ((const float4*)b1)[c];
    float4 h;
    h.x = fmaxf(fmaf(acc.x, nd, b.x), 0.f) * ns;
    h.y = fmaxf(fmaf(acc.y, nd, b.y), 0.f) * ns;
    h.z = fmaxf(fmaf(acc.z, nd, b.z), 0.f) * ns;
    h.w = fmaxf(fmaf(acc.w, nd, b.w), 0.f) * ns;
    ((float4*)g_h)[(size_t)node * 16 + c] = h;
}

// ---------------- GEMM 2: t2 = h @ W2   (64 -> 32) ----------------
// 256 threads, 256 nodes/block. 4 nodes x 8 cols per thread.
__global__ __launch_bounds__(256, 2) void gemm2_kernel(const float* __restrict__ W2, int n) {
    __shared__ float sW[64 * 32];            // 8 KB
    extern __shared__ float sX[];            // 69632 B
    int tid = threadIdx.x;
    int nb = blockIdx.x * 256;

    const float4* W4 = (const float4*)W2;
    float4* sW4 = (float4*)sW;
    #pragma unroll
    for (int idx = tid; idx < 64 * 8; idx += 256) sW4[idx] = W4[idx];

    const float4* h4 = (const float4*)g_h;
    #pragma unroll 4
    for (int idx = tid; idx < 256 * 16; idx += 256) {
        int row = idx >> 4;
        int c = idx & 15;
        int node = nb + row;
        float4 v = make_float4(0.f, 0.f, 0.f, 0.f);
        if (node < n) v = h4[(size_t)node * 16 + c];
        *(float4*)&sX[row * XPAD + c * 4] = v;
    }
    __syncthreads();

    int trow = tid >> 2;    // 0..63
    int jq = tid & 3;       // 8-col group
    float4 acc[4][2] = {};

    #pragma unroll 4
    for (int k = 0; k < 64; k++) {
        float a[4];
        #pragma unroll
        for (int i = 0; i < 4; i++) a[i] = sX[(trow + 64 * i) * XPAD + k];
        const float4* wr = (const float4*)&sW[k * 32 + jq * 8];
        float4 w0 = wr[0], w1 = wr[1];
        #pragma unroll
        for (int i = 0; i < 4; i++) {
            acc[i][0].x += a[i] * w0.x; acc[i][0].y += a[i] * w0.y;
            acc[i][0].z += a[i] * w0.z; acc[i][0].w += a[i] * w0.w;
            acc[i][1].x += a[i] * w1.x; acc[i][1].y += a[i] * w1.y;
            acc[i][1].z += a[i] * w1.z; acc[i][1].w += a[i] * w1.w;
        }
    }

    #pragma unroll
    for (int i = 0; i < 4; i++) {
        int node = nb + trow + 64 * i;
        if (node < n) {
            float4* o = (float4*)&g_t2[(size_t)node * 32 + jq * 8];
            o[0] = acc[i][0]; o[1] = acc[i][1];
        }
    }
}

// ---------------- gather 2: out = relu((sum t2[src]) * nd + b2) ----------------
// 8 threads/node, 32 nodes/block. Writes every output row exactly once.
__global__ __launch_bounds__(256) void gather2_kernel(const float* __restrict__ b2,
                                                      float* __restrict__ out, int n) {
    int tid = threadIdx.x;
    int node = blockIdx.x * 32 + (tid >> 3);
    if (node >= n) return;
    int c = tid & 7;
    const float4* t24 = (const float4*)g_t2;
    int start = g_roff[node];
    int len = g_indeg[node];
    float4 acc = make_float4(0.f, 0.f, 0.f, 0.f);
    int j = 0;
    for (; j + 2 <= len; j += 2) {
        int s0 = g_esrc[start + j];
        int s1 = g_esrc[start + j + 1];
        float4 v0 = t24[(size_t)s0 * 8 + c];
        float4 v1 = t24[(size_t)s1 * 8 + c];
        acc.x += v0.x; acc.y += v0.y; acc.z += v0.z; acc.w += v0.w;
        acc.x += v1.x; acc.y += v1.y; acc.z += v1.z; acc.w += v1.w;
    }
    if (j < len) {
        int s0 = g_esrc[start + j];
        float4 v0 = t24[(size_t)s0 * 8 + c];
        acc.x += v0.x; acc.y += v0.y; acc.z += v0.z; acc.w += v0.w;
    }
    float nd = g_deg[N_MAX + node];
    float4 b = ((const float4*)b2)[c];
    float4 o;
    o.x = fmaxf(fmaf(acc.x, nd, b.x), 0.f);
    o.y = fmaxf(fmaf(acc.y, nd, b.y), 0.f);
    o.z = fmaxf(fmaf(acc.z, nd, b.z), 0.f);
    o.w = fmaxf(fmaf(acc.w, nd, b.w), 0.f);
    ((float4*)out)[(size_t)node * 8 + c] = o;
}

// ---------------- launch ----------------
extern "C" void kernel_launch(void* const* d_in, const int* in_sizes, int n_in,
                              void* d_out, int out_size) {
    const float* x  = (const float*)d_in[0];
    const int*   ei = (const int*)d_in[1];
    const float* W1 = (const float*)d_in[2];
    const float* b1 = (const float*)d_in[3];
    const float* W2 = (const float*)d_in[4];
    const float* b2 = (const float*)d_in[5];
    float* out = (float*)d_out;

    int n = in_sizes[0] / F_IN;     // 100000
    int e = in_sizes[1] / 2;        // 1000000
    const int* src = ei;
    const int* dst = ei + e;

    const int SX_BYTES = 256 * XPAD * 4;    // 69632
    cudaFuncSetAttribute(gemm1_kernel, cudaFuncAttributeMaxDynamicSharedMemorySize, SX_BYTES);
    cudaFuncSetAttribute(gemm2_kernel, cudaFuncAttributeMaxDynamicSharedMemorySize, SX_BYTES);

    int nscan = (n + SCAN_B - 1) / SCAN_B;  // 196

    zero_kernel<<<(N_MAX + 255) / 256, 256>>>();
    count_kernel<<<(e + 255) / 256, 256>>>(src, dst, e);
    scan1_kernel<<<nscan, SCAN_B>>>(n);
    scan2_kernel<<<1, 256>>>(nscan);
    scan3_kernel<<<(n + 255) / 256, 256>>>(n);
    fill_kernel<<<(e + 255) / 256, 256>>>(src, dst, e);
    norm_kernel<<<(n + 255) / 256, 256>>>(n);

    gemm1_kernel<<<(n + 255) / 256, 256, SX_BYTES>>>(x, W1, n);
    gather1_kernel<<<(n + 15) / 16, 256>>>(b1, n);
    gemm2_kernel<<<(n + 255) / 256, 256, SX_BYTES>>>(W2, n);
    gather2_kernel<<<(n + 31) / 32, 256>>>(b2, out, n);
}